// round 16
// baseline (speedup 1.0000x reference)
#include <cuda_runtime.h>
#include <cstdint>

// MTF_68461778698457: Markov Transition Field
// x: (N=4096, C=4, L=256) f32  ->  out: (N, C, 65, 65) f32
//
// One WARP per row, 8 rows per 256-thread CTA.
// u32 orderable-float register bitonic sort with SEPARATE payload register
// (original index). ~17% fewer sort ops than the u64 fused-key version.
// Rows with exact duplicate floats (~16/16384) corrupt payloads on ties ->
// detected post-sort (keys still sort correctly) and re-ranked by an exact
// O(L^2) stable count (bit-exact). Phase 2: warp-local u8 histogram with
// match_any dedup, single coalesced float4 output stream.
//
// Numerics (locked, rel_err == 0.0): reference division == classical
// div.full.f32 Newton expansion; refined reciprocal r1(b) hoisted, mul.rn.

constexpr int L    = 256;
constexpr int NB   = 65;
constexpr int NB2  = NB * NB;        // 4225
constexpr int RPC  = 8;              // rows per CTA (one per warp)
constexpr int HPAD = 4240;           // u8 hist row bytes, 16B mult, >= 4228
constexpr int SENT = 4300;           // sentinel code for invalid transitions
constexpr unsigned int INVK = 0xFFFFFFFFu;

__device__ __forceinline__ float refined_rcp(float b)
{
    float r;
    asm("{\n\t"
        ".reg .f32 r0, e;\n\t"
        "rcp.approx.f32 r0, %1;\n\t"
        "fma.rn.f32 e, %1, r0, 0fBF800000;\n\t"   // e' = b*r0 - 1
        "neg.f32 e, e;\n\t"                        // e  = 1 - b*r0
        "fma.rn.f32 %0, r0, e, r0;\n\t"            // r1 = r0 + r0*e
        "}"
        : "=f"(r) : "f"(b));
    return r;
}

// Exact u8 -> f32 without I2F: bits(2^23 + c) == 0x4B000000 | c for c<256.
__device__ __forceinline__ float u8_to_f32(unsigned int packed, int sel)
{
    unsigned int b = __byte_perm(packed, 0x4B000000u, 0x7540 + sel);
    return __uint_as_float(b) - 8388608.0f;    // exact (float)c
}

__global__ __launch_bounds__(256, 5)
void mtf_kernel(const float* __restrict__ x, float* __restrict__ out)
{
    __shared__ __align__(16) unsigned char shist[RPC][HPAD];  // 33.1 KB
    __shared__ __align__(16) unsigned char sbin[RPC][272];    //  2.2 KB

    const int t    = threadIdx.x;
    const int w    = t >> 5;
    const int lane = t & 31;
    const long long rowg = (long long)blockIdx.x * RPC + w;

    unsigned int* hw32 = (unsigned int*)shist[w];

    // ---- zero this warp's u8 histogram (warp-private) ---------------------
    {
        uint4* h4 = (uint4*)shist[w];
        const uint4 z = make_uint4(0u, 0u, 0u, 0u);
        #pragma unroll
        for (int i = lane; i < HPAD / 16; i += 32) h4[i] = z;
    }

    // ---- Phase 1: load, range scan, u32 keys + payload ---------------------
    const float* xr = x + rowg * L + lane * 8;
    float4 va = *(const float4*)(xr);
    float4 vb = *(const float4*)(xr + 4);
    float v[8] = { va.x, va.y, va.z, va.w, vb.x, vb.y, vb.z, vb.w };

    int locF = 256, locE = -1;
    #pragma unroll
    for (int i = 0; i < 8; i++) {
        int idx = lane * 8 + i;
        if (v[i] != 0.0f) {
            if (idx < locF) locF = idx;
            if (idx > locE) locE = idx;
        }
    }
    const int first = __reduce_min_sync(0xffffffffu, locF);
    const int last  = __reduce_max_sync(0xffffffffu, locE);
    const bool has  = (last >= first);
    const int  vl   = has ? (last - first + 1) : 1;

    unsigned int key[8], pay[8];
    #pragma unroll
    for (int i = 0; i < 8; i++) {
        int idx = lane * 8 + i;
        unsigned int u = __float_as_uint(v[i]);
        unsigned int o = (u & 0x80000000u) ? ~u : (u | 0x80000000u);
        bool valid = has && (idx >= first) && (idx <= last);
        key[i] = valid ? o : INVK;
        pay[i] = (unsigned int)idx;
    }

    // ---- u32 bitonic sort, payload tags along ------------------------------
    #define CE(a, b, asc)                                                    \
        do {                                                                 \
            bool _sw = (key[a] > key[b]) == (asc);                           \
            unsigned int _ka = key[a], _kb = key[b];                         \
            unsigned int _pa = pay[a], _pb = pay[b];                         \
            key[a] = _sw ? _kb : _ka;  key[b] = _sw ? _ka : _kb;             \
            pay[a] = _sw ? _pb : _pa;  pay[b] = _sw ? _pa : _pb;             \
        } while (0)

    #define STAGE_SHFL(off, asc)                                             \
        do {                                                                 \
            bool _keepMin = ((asc) == ((lane & (off)) == 0));                \
            _Pragma("unroll")                                                \
            for (int _i = 0; _i < 8; _i++) {                                 \
                unsigned int _ok =                                           \
                    __shfl_xor_sync(0xffffffffu, key[_i], (off));            \
                unsigned int _op =                                           \
                    __shfl_xor_sync(0xffffffffu, pay[_i], (off));            \
                bool _take = (_ok < key[_i]) == _keepMin;                    \
                key[_i] = _take ? _ok : key[_i];                             \
                pay[_i] = _take ? _op : pay[_i];                             \
            }                                                                \
        } while (0)

    #define LOCAL3(asc)                                                      \
        do {                                                                 \
            CE(0,4,asc); CE(1,5,asc); CE(2,6,asc); CE(3,7,asc);              \
            CE(0,2,asc); CE(1,3,asc); CE(4,6,asc); CE(5,7,asc);              \
            CE(0,1,asc); CE(2,3,asc); CE(4,5,asc); CE(6,7,asc);              \
        } while (0)

    CE(0,1,true); CE(2,3,false); CE(4,5,true); CE(6,7,false);
    CE(0,2,true); CE(1,3,true);  CE(4,6,false); CE(5,7,false);
    CE(0,1,true); CE(2,3,true);  CE(4,5,false); CE(6,7,false);
    { bool a = (lane & 1) == 0; LOCAL3(a); }
    { bool a = (lane & 2) == 0; STAGE_SHFL(1, a); LOCAL3(a); }
    { bool a = (lane & 4) == 0; STAGE_SHFL(2, a); STAGE_SHFL(1, a); LOCAL3(a); }
    { bool a = (lane & 8) == 0; STAGE_SHFL(4, a); STAGE_SHFL(2, a);
      STAGE_SHFL(1, a); LOCAL3(a); }
    { bool a = (lane & 16) == 0; STAGE_SHFL(8, a); STAGE_SHFL(4, a);
      STAGE_SHFL(2, a); STAGE_SHFL(1, a); LOCAL3(a); }
    { STAGE_SHFL(16, true); STAGE_SHFL(8, true); STAGE_SHFL(4, true);
      STAGE_SHFL(2, true); STAGE_SHFL(1, true); LOCAL3(true); }

    #undef CE
    #undef STAGE_SHFL
    #undef LOCAL3

    // duplicate detection among VALID keys (keys are correctly sorted even
    // if payloads got scrambled by ties; equal keys are adjacent).
    bool dupl = false;
    #pragma unroll
    for (int i = 0; i < 7; i++)
        dupl |= (key[i] == key[i + 1]) && (key[i] != INVK);
    {
        unsigned int nxt0 = __shfl_down_sync(0xffffffffu, key[0], 1);
        if (lane < 31) dupl |= (key[7] == nxt0) && (key[7] != INVK);
    }
    const bool anydup = __any_sync(0xffffffffu, dupl);

    if (!anydup) {
        // ---- fast path: rank = sorted position 8*lane+i, scatter via pay --
        const float rinv = refined_rcp((float)vl);        // r1(vl)
        const float base = (float)(lane * 8);             // one I2F
        #pragma unroll
        for (int i = 0; i < 8; i++) {
            int r = lane * 8 + i;
            if (r < vl) {
                float fr = base + (float)i;               // exact FADD (<256)
                float q  = __fmul_rn(fr, rinv);           // == div.full(r,vl)
                float rb = __fmul_rn(q, 65.0f);
                int bi = (int)rb;                         // trunc
                bi = bi > (NB - 1) ? (NB - 1) : bi;
                sbin[w][pay[i]] = (unsigned char)bi;
            }
        }
    } else {
        // ---- slow path (~16 rows/16384): exact stable O(L^2) rank ---------
        // Scratch: first 256 words of this warp's hist row (re-zeroed after).
        const float* xr2 = x + rowg * L + lane * 8;
        float4 ra = *(const float4*)(xr2);
        float4 rb4 = *(const float4*)(xr2 + 4);
        float v2[8] = { ra.x, ra.y, ra.z, ra.w, rb4.x, rb4.y, rb4.z, rb4.w };
        #pragma unroll
        for (int i = 0; i < 8; i++) {
            int idx = lane * 8 + i;
            unsigned int u = __float_as_uint(v2[i]);
            unsigned int o = (u & 0x80000000u) ? ~u : (u | 0x80000000u);
            bool valid = has && (idx >= first) && (idx <= last);
            hw32[idx] = valid ? o : INVK;
        }
        __syncwarp();
        const float rinv = refined_rcp((float)vl);
        #pragma unroll
        for (int i = 0; i < 8; i++) {
            const int idx = lane * 8 + i;
            const unsigned int k = hw32[idx];
            if (k != INVK) {
                int r = 0;
                for (int j = 0; j < L; j++) {
                    unsigned int kj = hw32[j];
                    r += (kj < k) || (kj == k && j < idx);
                }
                float q  = __fmul_rn((float)r, rinv);
                float rb = __fmul_rn(q, 65.0f);
                int bi = (int)rb;
                bi = bi > (NB - 1) ? (NB - 1) : bi;
                sbin[w][idx] = (unsigned char)bi;
            }
        }
        __syncwarp();
        // re-zero scratch (words 0..255 = 64 uint4)
        uint4* h4 = (uint4*)shist[w];
        const uint4 z = make_uint4(0u, 0u, 0u, 0u);
        #pragma unroll
        for (int i = lane; i < 64; i += 32) h4[i] = z;
    }
    __syncwarp();        // sbin + zeroed hist visible within warp

    // ---- Phase 2 (warp-local): codes, match-dedup u8 hist -----------------
    int code[8];
    {
        const uint2 bw = *(const uint2*)&sbin[w][lane * 8];
        const unsigned int b8 = sbin[w][lane * 8 + 8];    // padded row, safe
        const int bl[8] = {
            (int)( bw.x        & 0xffu), (int)((bw.x >>  8) & 0xffu),
            (int)((bw.x >> 16) & 0xffu), (int)((bw.x >> 24) & 0xffu),
            (int)( bw.y        & 0xffu), (int)((bw.y >>  8) & 0xffu),
            (int)((bw.y >> 16) & 0xffu), (int)((bw.y >> 24) & 0xffu)
        };
        #pragma unroll
        for (int i = 0; i < 8; i++) {
            int tt = lane * 8 + i;
            bool tr = (tt >= first) && (tt < last);       // both ends valid
            int nb = (i < 7) ? bl[i + 1] : (int)b8;
            code[i] = tr ? (bl[i] * NB + nb) : SENT;
        }
    }

    #pragma unroll
    for (int i = 0; i < 8; i++) {
        unsigned int mask = __match_any_sync(0xffffffffu, code[i]);
        int cnt = __popc(mask);
        int leader = __ffs(mask) - 1;
        if (lane == leader && code[i] != SENT) {
            shist[w][code[i]] = (unsigned char)(shist[w][code[i]] + cnt);
        }
        __syncwarp();
    }

    // ---- Stream the full row out, coalesced float4, single write ----------
    {
        int nrm = vl - 1; if (nrm < 1) nrm = 1;
        const float rnorm = refined_rcp((float)nrm);      // r1(norm)
        const size_t p0 = (size_t)rowg * NB2;
        float* op = out + p0;
        const int lead = (int)((4 - (p0 & 3)) & 3);       // floats to peel
        const int rem  = NB2 - lead;
        const int nv   = rem >> 2;                        // float4 count
        const int tail = rem & 3;
        const int sh   = 8 * lead;

        if (lane < lead)
            op[lane] = __fmul_rn((float)shist[w][lane], rnorm);

        for (int i = lane; i < nv; i += 32) {
            unsigned int lo = hw32[i];
            unsigned int hi = hw32[i + 1];                // HPAD pad: in-bounds
            unsigned int c4 = (sh == 0) ? lo : __funnelshift_r(lo, hi, sh);
            float4 wv;
            wv.x = __fmul_rn(u8_to_f32(c4, 0), rnorm);
            wv.y = __fmul_rn(u8_to_f32(c4, 1), rnorm);
            wv.z = __fmul_rn(u8_to_f32(c4, 2), rnorm);
            wv.w = __fmul_rn(u8_to_f32(c4, 3), rnorm);
            *(float4*)(op + lead + 4 * i) = wv;
        }
        if (lane < tail) {
            int f = lead + 4 * nv + lane;
            op[f] = __fmul_rn((float)shist[w][f], rnorm);
        }
    }
}

extern "C" void kernel_launch(void* const* d_in, const int* in_sizes, int n_in,
                              void* d_out, int out_size)
{
    const float* x = (const float*)d_in[0];
    float* out = (float*)d_out;
    const int nrows = in_sizes[0] / L;       // N*C = 16384 (divisible by 8)
    mtf_kernel<<<nrows / RPC, 256>>>(x, out);
}

// round 17
// speedup vs baseline: 1.4599x; 1.4599x over previous
#include <cuda_runtime.h>
#include <cstdint>

// MTF_68461778698457: Markov Transition Field
// x: (N=4096, C=4, L=256) f32  ->  out: (N, C, 65, 65) f32
//
// One WARP per row (8 elems/thread u64 register bitonic sort), 5 rows per
// 160-thread CTA. RPC=5 makes the smem allocation round to 24KB on the 8KB
// grain -> 9 CTAs/SM = 45 warps (70%) instead of the 40-warp ceiling the
// 8-warp CTA hits (36KB->40KB->5 CTAs). No CTA-wide barriers, so the
// ragged last CTA just early-returns surplus warps.
// Phase 2 warp-local: u8 histogram with match_any dedup (no atomics),
// single coalesced float4 output stream, PRMT-based u8->f32.
//
// Numerics (locked, rel_err == 0.0): reference division == classical
// div.full.f32 Newton expansion; refined reciprocal r1(b) hoisted, mul.rn.

constexpr int L    = 256;
constexpr int NB   = 65;
constexpr int NB2  = NB * NB;        // 4225
constexpr int RPC  = 5;              // rows per CTA (one per warp)
constexpr int THREADS = RPC * 32;    // 160
constexpr int HPAD = 4240;           // u8 hist row bytes, 16B mult, >= 4228
constexpr int SENT = 4300;           // sentinel code for invalid transitions

__device__ __forceinline__ float refined_rcp(float b)
{
    float r;
    asm("{\n\t"
        ".reg .f32 r0, e;\n\t"
        "rcp.approx.f32 r0, %1;\n\t"
        "fma.rn.f32 e, %1, r0, 0fBF800000;\n\t"   // e' = b*r0 - 1
        "neg.f32 e, e;\n\t"                        // e  = 1 - b*r0
        "fma.rn.f32 %0, r0, e, r0;\n\t"            // r1 = r0 + r0*e
        "}"
        : "=f"(r) : "f"(b));
    return r;
}

// Exact u8 -> f32 without I2F: bits(2^23 + c) == 0x4B000000 | c for c<256.
__device__ __forceinline__ float u8_to_f32(unsigned int packed, int sel)
{
    unsigned int b = __byte_perm(packed, 0x4B000000u, 0x7540 + sel);
    return __uint_as_float(b) - 8388608.0f;    // exact (float)c
}

__global__ __launch_bounds__(THREADS, 9)
void mtf_kernel(const float* __restrict__ x, float* __restrict__ out,
                int nrows)
{
    __shared__ __align__(16) unsigned char shist[RPC][HPAD];  // 21200 B
    __shared__ __align__(16) unsigned char sbin[RPC][272];    //  1360 B

    const int t    = threadIdx.x;
    const int w    = t >> 5;          // 0..4
    const int lane = t & 31;
    const long long rowg = (long long)blockIdx.x * RPC + w;
    if (rowg >= nrows) return;        // ragged tail; no CTA barriers exist

    // ---- zero this warp's u8 histogram (warp-private) ---------------------
    {
        uint4* h4 = (uint4*)shist[w];
        const uint4 z = make_uint4(0u, 0u, 0u, 0u);
        #pragma unroll
        for (int i = lane; i < HPAD / 16; i += 32) h4[i] = z;
    }

    // ---- Phase 1: load, range scan, register bitonic sort ------------------
    const float* xr = x + rowg * L + lane * 8;
    float4 va = *(const float4*)(xr);
    float4 vb = *(const float4*)(xr + 4);
    float v[8] = { va.x, va.y, va.z, va.w, vb.x, vb.y, vb.z, vb.w };

    int locF = 256, locE = -1;
    #pragma unroll
    for (int i = 0; i < 8; i++) {
        int idx = lane * 8 + i;
        if (v[i] != 0.0f) {
            if (idx < locF) locF = idx;
            if (idx > locE) locE = idx;
        }
    }
    const int first = __reduce_min_sync(0xffffffffu, locF);
    const int last  = __reduce_max_sync(0xffffffffu, locE);
    const bool has  = (last >= first);
    const int  vl   = has ? (last - first + 1) : 1;

    unsigned long long key[8];
    #pragma unroll
    for (int i = 0; i < 8; i++) {
        int idx = lane * 8 + i;
        unsigned int u = __float_as_uint(v[i]);
        unsigned int o = (u & 0x80000000u) ? ~u : (u | 0x80000000u);
        bool valid = has && (idx >= first) && (idx <= last);
        key[i] = valid ? ((((unsigned long long)o) << 32) | (unsigned)idx)
                       : 0xFFFFFFFFFFFFFFFFull;
    }

    #define CE(a, b, asc)                                                    \
        do {                                                                 \
            if ((key[a] > key[b]) == (asc)) {                                \
                unsigned long long _tmp = key[a];                            \
                key[a] = key[b]; key[b] = _tmp;                              \
            }                                                                \
        } while (0)

    #define STAGE_SHFL(off, asc)                                             \
        do {                                                                 \
            bool _keepMin = ((asc) == ((lane & (off)) == 0));                \
            _Pragma("unroll")                                                \
            for (int _i = 0; _i < 8; _i++) {                                 \
                unsigned long long _o =                                      \
                    __shfl_xor_sync(0xffffffffu, key[_i], (off));            \
                bool _take = (_o < key[_i]) == _keepMin;                     \
                key[_i] = _take ? _o : key[_i];                              \
            }                                                                \
        } while (0)

    #define LOCAL3(asc)                                                      \
        do {                                                                 \
            CE(0,4,asc); CE(1,5,asc); CE(2,6,asc); CE(3,7,asc);              \
            CE(0,2,asc); CE(1,3,asc); CE(4,6,asc); CE(5,7,asc);              \
            CE(0,1,asc); CE(2,3,asc); CE(4,5,asc); CE(6,7,asc);              \
        } while (0)

    CE(0,1,true); CE(2,3,false); CE(4,5,true); CE(6,7,false);
    CE(0,2,true); CE(1,3,true);  CE(4,6,false); CE(5,7,false);
    CE(0,1,true); CE(2,3,true);  CE(4,5,false); CE(6,7,false);
    { bool a = (lane & 1) == 0; LOCAL3(a); }
    { bool a = (lane & 2) == 0; STAGE_SHFL(1, a); LOCAL3(a); }
    { bool a = (lane & 4) == 0; STAGE_SHFL(2, a); STAGE_SHFL(1, a); LOCAL3(a); }
    { bool a = (lane & 8) == 0; STAGE_SHFL(4, a); STAGE_SHFL(2, a);
      STAGE_SHFL(1, a); LOCAL3(a); }
    { bool a = (lane & 16) == 0; STAGE_SHFL(8, a); STAGE_SHFL(4, a);
      STAGE_SHFL(2, a); STAGE_SHFL(1, a); LOCAL3(a); }
    { STAGE_SHFL(16, true); STAGE_SHFL(8, true); STAGE_SHFL(4, true);
      STAGE_SHFL(2, true); STAGE_SHFL(1, true); LOCAL3(true); }

    #undef CE
    #undef STAGE_SHFL
    #undef LOCAL3

    // rank of element in key[i] is 8*lane + i; valid ranks are [0, vl)
    {
        const float rinv = refined_rcp((float)vl);        // r1(vl)
        const float base = (float)(lane * 8);             // one I2F
        #pragma unroll
        for (int i = 0; i < 8; i++) {
            int r = lane * 8 + i;
            if (r < vl) {
                float fr = base + (float)i;               // exact FADD (<256)
                float q  = __fmul_rn(fr, rinv);           // == div.full(r,vl)
                float rb = __fmul_rn(q, 65.0f);
                int bi = (int)rb;                         // trunc
                bi = bi > (NB - 1) ? (NB - 1) : bi;
                sbin[w][key[i] & 0xffu] = (unsigned char)bi;
            }
        }
    }
    __syncwarp();        // sbin + zeroed hist visible within warp

    // ---- Phase 2 (warp-local): codes, match-dedup u8 hist -----------------
    int code[8];
    {
        const uint2 bw = *(const uint2*)&sbin[w][lane * 8];
        const unsigned int b8 = sbin[w][lane * 8 + 8];    // padded row, safe
        const int bl[8] = {
            (int)( bw.x        & 0xffu), (int)((bw.x >>  8) & 0xffu),
            (int)((bw.x >> 16) & 0xffu), (int)((bw.x >> 24) & 0xffu),
            (int)( bw.y        & 0xffu), (int)((bw.y >>  8) & 0xffu),
            (int)((bw.y >> 16) & 0xffu), (int)((bw.y >> 24) & 0xffu)
        };
        #pragma unroll
        for (int i = 0; i < 8; i++) {
            int tt = lane * 8 + i;
            bool tr = (tt >= first) && (tt < last);       // both ends valid
            int nb = (i < 7) ? bl[i + 1] : (int)b8;
            code[i] = tr ? (bl[i] * NB + nb) : SENT;
        }
    }

    #pragma unroll
    for (int i = 0; i < 8; i++) {
        unsigned int mask = __match_any_sync(0xffffffffu, code[i]);
        int cnt = __popc(mask);
        int leader = __ffs(mask) - 1;
        if (lane == leader && code[i] != SENT) {
            shist[w][code[i]] = (unsigned char)(shist[w][code[i]] + cnt);
        }
        __syncwarp();
    }

    // ---- Stream the full row out, coalesced float4, single write ----------
    {
        int nrm = vl - 1; if (nrm < 1) nrm = 1;
        const float rnorm = refined_rcp((float)nrm);      // r1(norm)
        const size_t p0 = (size_t)rowg * NB2;
        float* op = out + p0;
        const int lead = (int)((4 - (p0 & 3)) & 3);       // floats to peel
        const int rem  = NB2 - lead;
        const int nv   = rem >> 2;                        // float4 count
        const int tail = rem & 3;
        const unsigned int* hw = (const unsigned int*)shist[w];
        const int sh = 8 * lead;

        if (lane < lead)
            op[lane] = __fmul_rn((float)shist[w][lane], rnorm);

        for (int i = lane; i < nv; i += 32) {
            unsigned int lo = hw[i];
            unsigned int hi = hw[i + 1];                  // HPAD pad: in-bounds
            unsigned int c4 = (sh == 0) ? lo : __funnelshift_r(lo, hi, sh);
            float4 wv;
            wv.x = __fmul_rn(u8_to_f32(c4, 0), rnorm);
            wv.y = __fmul_rn(u8_to_f32(c4, 1), rnorm);
            wv.z = __fmul_rn(u8_to_f32(c4, 2), rnorm);
            wv.w = __fmul_rn(u8_to_f32(c4, 3), rnorm);
            *(float4*)(op + lead + 4 * i) = wv;
        }
        if (lane < tail) {
            int f = lead + 4 * nv + lane;
            op[f] = __fmul_rn((float)shist[w][f], rnorm);
        }
    }
}

extern "C" void kernel_launch(void* const* d_in, const int* in_sizes, int n_in,
                              void* d_out, int out_size)
{
    const float* x = (const float*)d_in[0];
    float* out = (float*)d_out;
    const int nrows = in_sizes[0] / L;               // N*C = 16384
    const int grid  = (nrows + RPC - 1) / RPC;       // 3277
    mtf_kernel<<<grid, THREADS>>>(x, out, nrows);
}